// round 4
// baseline (speedup 1.0000x reference)
#include <cuda_runtime.h>
#include <math.h>

// ---- problem dims ----
#define NB 48
#define NA 16
#define LL 768            // NB*NA
#define QKVW 384
#define MPOST 2240        // 2208 valid post-attention rows padded to 70*32

// output layout in d_out (floats): policy_flat | q_values | eo
#define OUT_POLICY 0
#define OUT_Q      24576
#define OUT_EO     25344

// ---- scratch ----
__device__ __align__(256) float g_eoea[1536 * 128];
__device__ __align__(256) float g_x1d[1536 * 128];
__device__ __align__(256) float g_qkvd[1536 * QKVW];
__device__ __align__(256) float g_aod[MPOST * 128];   // zero-init: pad rows stay 0
__device__ __align__(256) float g_qvd[MPOST];

// residual-gather map: post-row m -> x1d row
__device__ __forceinline__ int res_map(int m) {
    if (m < 768) return m;
    int t = m - 768;
    if (t >= 1440) return 0;
    int k = t / 96 + 1;
    int r = t % 96;
    int b = r >> 1, c = r & 1;
    int j = c ? (k - 1) : k;
    return 768 + b * 16 + j;
}

// ============================================================================
// chunk_gemm: 32 rows (resident, transposed in smem, stride 33) x 64 cols,
// W streamed from gmem double-buffered. acc[2][4] per thread (16x16 thread grid).
// All 256 threads must call (contains __syncthreads).
// ============================================================================
__device__ __forceinline__ void chunk_gemm(
    const float (*At)[33], const float* __restrict__ wrow, int K,
    float (*Ws)[16][64], float acc[2][4])
{
    const int tid = threadIdx.x;
    const int tx = tid & 15, ty = tid >> 4;
    const int lr = tid >> 2;
    const int lc = (tid & 3) * 4;

#pragma unroll
    for (int i = 0; i < 2; i++)
#pragma unroll
        for (int j = 0; j < 4; j++) acc[i][j] = 0.f;

    __syncthreads();   // Ws reuse + At readiness
    float4 w = wrow ? *(const float4*)(wrow + lc) : make_float4(0.f, 0.f, 0.f, 0.f);
    Ws[0][lc + 0][lr] = w.x; Ws[0][lc + 1][lr] = w.y;
    Ws[0][lc + 2][lr] = w.z; Ws[0][lc + 3][lr] = w.w;
    __syncthreads();

    int buf = 0;
    const int KT = K >> 4;
    for (int kt = 0; kt < KT; kt++) {
        const bool nx = (kt + 1 < KT);
        if (nx && wrow) w = *(const float4*)(wrow + (kt + 1) * 16 + lc);
#pragma unroll
        for (int kk = 0; kk < 16; kk++) {
            const int k = kt * 16 + kk;
            const float a0 = At[k][ty * 2];
            const float a1 = At[k][ty * 2 + 1];
            const float4 b = *(const float4*)&Ws[buf][kk][tx * 4];
            acc[0][0] += a0 * b.x; acc[0][1] += a0 * b.y; acc[0][2] += a0 * b.z; acc[0][3] += a0 * b.w;
            acc[1][0] += a1 * b.x; acc[1][1] += a1 * b.y; acc[1][2] += a1 * b.z; acc[1][3] += a1 * b.w;
        }
        if (nx) {
            const int nb = buf ^ 1;
            Ws[nb][lc + 0][lr] = w.x; Ws[nb][lc + 1][lr] = w.y;
            Ws[nb][lc + 2][lr] = w.z; Ws[nb][lc + 3][lr] = w.w;
            __syncthreads();
            buf = nb;
        }
    }
}

// load 32 rows x 128 cols from row-major gmem into transposed smem [128][33]
__device__ __forceinline__ void load_rows_t(const float* __restrict__ src, int row0,
                                            int stride, float (*At)[33])
{
    const int tid = threadIdx.x;
#pragma unroll
    for (int t = 0; t < 4; t++) {
        const int f = tid + t * 256;          // 0..1023
        const int r = f >> 5, c = (f & 31) * 4;
        float4 v = *(const float4*)(src + (size_t)(row0 + r) * stride + c);
        At[c + 0][r] = v.x; At[c + 1][r] = v.y;
        At[c + 2][r] = v.z; At[c + 3][r] = v.w;
    }
}

// ============================================================================
// K1: fused front chain. 24 CTAs x 32 rows.
// obs -> H1(leaky) -> H2(leaky) -> policy(gelu) ; eo ; ea = [obs|pol]@eaw
// ============================================================================
struct FrontSmem {
    float At[160][33];    // obs (0..127) + policy (128..159)
    float H1t[256][33];
    float H2t[128][33];
    float Ws[2][16][64];
};

__global__ void __launch_bounds__(256)
fused_front(const float* __restrict__ obs,
            const float* __restrict__ aw1, const float* __restrict__ ab1,
            const float* __restrict__ aw2, const float* __restrict__ ab2,
            const float* __restrict__ aw3, const float* __restrict__ ab3,
            const float* __restrict__ eow, const float* __restrict__ eob,
            const float* __restrict__ eaw, const float* __restrict__ eab,
            float* __restrict__ out_eo, float* __restrict__ out_policy,
            float* __restrict__ eoea)
{
    extern __shared__ char raw[];
    FrontSmem& sm = *reinterpret_cast<FrontSmem*>(raw);
    const int tid = threadIdx.x;
    const int tx = tid & 15, ty = tid >> 4;
    const int lr = tid >> 2;
    const int row0 = blockIdx.x * 32;

    load_rows_t(obs, row0, 128, sm.At);

    // ---- stage 1: [aw1 | eow], N=384, K=128 ----
    for (int c = 0; c < 6; c++) {
        const int nl = c * 64 + lr;
        const float* wrow = (nl < 256) ? aw1 + (size_t)nl * 128
                                       : eow + (size_t)(nl - 256) * 128;
        float acc[2][4];
        chunk_gemm(sm.At, wrow, 128, sm.Ws, acc);
        if (c < 4) {
#pragma unroll
            for (int i = 0; i < 2; i++) {
                const int r = ty * 2 + i;
#pragma unroll
                for (int j = 0; j < 4; j++) {
                    const int n = c * 64 + tx * 4 + j;
                    float v = acc[i][j] + ab1[n];
                    v = (v > 0.f) ? v : 0.01f * v;
                    sm.H1t[n][r] = v;
                }
            }
        } else {
#pragma unroll
            for (int i = 0; i < 2; i++) {
                const int r = ty * 2 + i, grow = row0 + r;
                float o[4];
#pragma unroll
                for (int j = 0; j < 4; j++)
                    o[j] = acc[i][j] + eob[(c - 4) * 64 + tx * 4 + j];
                const int off = grow * 128 + (c - 4) * 64 + tx * 4;
                *(float4*)(out_eo + off) = *(float4*)o;
                *(float4*)(eoea + off)   = *(float4*)o;
            }
        }
    }

    // ---- stage 2: H2 = leaky(H1 @ aw2^T), N=128, K=256 ----
    for (int c = 0; c < 2; c++) {
        const float* wrow = aw2 + (size_t)(c * 64 + lr) * 256;
        float acc[2][4];
        chunk_gemm(sm.H1t, wrow, 256, sm.Ws, acc);
#pragma unroll
        for (int i = 0; i < 2; i++) {
            const int r = ty * 2 + i;
#pragma unroll
            for (int j = 0; j < 4; j++) {
                const int n = c * 64 + tx * 4 + j;
                float v = acc[i][j] + ab2[n];
                v = (v > 0.f) ? v : 0.01f * v;
                sm.H2t[n][r] = v;
            }
        }
    }

    // ---- stage 3: policy = gelu(H2 @ aw3^T), N=32, K=128 ----
    {
        const float* wrow = (lr < 32) ? aw3 + (size_t)lr * 128 : nullptr;
        float acc[2][4];
        chunk_gemm(sm.H2t, wrow, 128, sm.Ws, acc);
        if (tx < 8) {
#pragma unroll
            for (int i = 0; i < 2; i++) {
                const int r = ty * 2 + i, grow = row0 + r;
                float o[4];
#pragma unroll
                for (int j = 0; j < 4; j++) {
                    const int n = tx * 4 + j;
                    float v = acc[i][j] + ab3[n];
                    v = 0.5f * v * (1.0f + erff(v * 0.70710678118654752f));
                    sm.At[128 + n][r] = v;
                    o[j] = v;
                }
                *(float4*)(out_policy + grow * 32 + tx * 4) = *(float4*)o;
            }
        }
    }

    // ---- stage 4: ea = [obs|policy] @ eaw^T, N=128, K=160 ----
    for (int c = 0; c < 2; c++) {
        const float* wrow = eaw + (size_t)(c * 64 + lr) * 160;
        float acc[2][4];
        chunk_gemm(sm.At, wrow, 160, sm.Ws, acc);
#pragma unroll
        for (int i = 0; i < 2; i++) {
            const int r = ty * 2 + i, grow = row0 + r;
            float o[4];
#pragma unroll
            for (int j = 0; j < 4; j++)
                o[j] = acc[i][j] + eab[c * 64 + tx * 4 + j];
            *(float4*)(eoea + (size_t)(768 + grow) * 128 + c * 64 + tx * 4) = *(float4*)o;
        }
    }
}

// ============================================================================
// K2: fused mid chain. 48 CTAs x 32 rows over 1536.
// x1 = relu(eoea @ riw^T)  (also to gmem for residual); qkv = x1 @ miw^T
// ============================================================================
struct MidSmem {
    float At[128][33];
    float X1t[128][33];
    float Ws[2][16][64];
};

__global__ void __launch_bounds__(256)
fused_mid(const float* __restrict__ eoea,
          const float* __restrict__ riw, const float* __restrict__ rib,
          const float* __restrict__ miw, const float* __restrict__ mib,
          float* __restrict__ x1d, float* __restrict__ qkvd)
{
    extern __shared__ char raw[];
    MidSmem& sm = *reinterpret_cast<MidSmem*>(raw);
    const int tid = threadIdx.x;
    const int tx = tid & 15, ty = tid >> 4;
    const int lr = tid >> 2;
    const int row0 = blockIdx.x * 32;

    load_rows_t(eoea, row0, 128, sm.At);

    for (int c = 0; c < 2; c++) {
        const float* wrow = riw + (size_t)(c * 64 + lr) * 128;
        float acc[2][4];
        chunk_gemm(sm.At, wrow, 128, sm.Ws, acc);
#pragma unroll
        for (int i = 0; i < 2; i++) {
            const int r = ty * 2 + i, grow = row0 + r;
            float o[4];
#pragma unroll
            for (int j = 0; j < 4; j++) {
                const int n = c * 64 + tx * 4 + j;
                float v = fmaxf(acc[i][j] + rib[n], 0.f);
                sm.X1t[n][r] = v;
                o[j] = v;
            }
            *(float4*)(x1d + (size_t)grow * 128 + c * 64 + tx * 4) = *(float4*)o;
        }
    }

    for (int c = 0; c < 6; c++) {
        const float* wrow = miw + (size_t)(c * 64 + lr) * 128;
        float acc[2][4];
        chunk_gemm(sm.X1t, wrow, 128, sm.Ws, acc);
#pragma unroll
        for (int i = 0; i < 2; i++) {
            const int r = ty * 2 + i, grow = row0 + r;
            float o[4];
#pragma unroll
            for (int j = 0; j < 4; j++)
                o[j] = acc[i][j] + mib[c * 64 + tx * 4 + j];
            *(float4*)(qkvd + (size_t)grow * QKVW + c * 64 + tx * 4) = *(float4*)o;
        }
    }
}

// ============================================================================
// K3: combined attention. blocks 0..47 = flash (k=0 slot), 48..107 = class attn
// ============================================================================
struct Flash64Smem {
    float Qs[32][68];
    float Ks[32][68];
    float Vs[64][36];
    float Ss[64][68];
    float Pt[64][68];
    float Ms[64], Ls[64], Cs[64];
};
struct ClsSmem {
    float Qc[96][36];
    float Kc[96][36];
    float Vc[96][36];
    float Sc[96][97];
};
union AttnSmem { Flash64Smem f; ClsSmem c; };

__global__ void __launch_bounds__(256)
attn_combined(const float* __restrict__ qkvd, float* __restrict__ aod)
{
    extern __shared__ char raw[];
    const int bx = blockIdx.x;
    const int tid = threadIdx.x;

    if (bx < 48) {
        Flash64Smem& sm = reinterpret_cast<AttnSmem*>(raw)->f;
        const int h = bx / 12;
        const int l0 = (bx % 12) * 64;
        const float* Qb = qkvd + h * 32;
        const float* Kb = qkvd + 128 + h * 32;
        const float* Vb = qkvd + 256 + h * 32;

#pragma unroll
        for (int t = 0; t < 2; t++) {
            const int f = tid + t * 256;
            const int r = f >> 3, c = (f & 7) * 4;
            float4 v = *(const float4*)(Qb + (size_t)(l0 + r) * QKVW + c);
            sm.Qs[c + 0][r] = v.x; sm.Qs[c + 1][r] = v.y;
            sm.Qs[c + 2][r] = v.z; sm.Qs[c + 3][r] = v.w;
        }
        if (tid < 64) { sm.Ms[tid] = -1e30f; sm.Ls[tid] = 0.f; }

        float O[2][4];
#pragma unroll
        for (int i = 0; i < 2; i++)
#pragma unroll
            for (int j = 0; j < 4; j++) O[i][j] = 0.f;

        const int txA = tid & 15, tyA = tid >> 4;
        const int rB = tid >> 2,  hB = tid & 3;
        const int txC = tid & 7,  tyC = tid >> 3;

        for (int m0 = 0; m0 < LL; m0 += 64) {
            __syncthreads();
#pragma unroll
            for (int t = 0; t < 2; t++) {
                const int f = tid + t * 256;
                const int r = f >> 3, c = (f & 7) * 4;
                float4 kv = *(const float4*)(Kb + (size_t)(m0 + r) * QKVW + c);
                sm.Ks[c + 0][r] = kv.x; sm.Ks[c + 1][r] = kv.y;
                sm.Ks[c + 2][r] = kv.z; sm.Ks[c + 3][r] = kv.w;
                float4 vv = *(const float4*)(Vb + (size_t)(m0 + r) * QKVW + c);
                *(float4*)&sm.Vs[r][c] = vv;
            }
            __syncthreads();

            float fa[4][4];
#pragma unroll
            for (int i = 0; i < 4; i++)
#pragma unroll
                for (int j = 0; j < 4; j++) fa[i][j] = 0.f;
#pragma unroll 8
            for (int d = 0; d < 32; d++) {
                float4 a = *(const float4*)&sm.Qs[d][tyA * 4];
                float4 b = *(const float4*)&sm.Ks[d][txA * 4];
                fa[0][0] += a.x * b.x; fa[0][1] += a.x * b.y; fa[0][2] += a.x * b.z; fa[0][3] += a.x * b.w;
                fa[1][0] += a.y * b.x; fa[1][1] += a.y * b.y; fa[1][2] += a.y * b.z; fa[1][3] += a.y * b.w;
                fa[2][0] += a.z * b.x; fa[2][1] += a.z * b.y; fa[2][2] += a.z * b.z; fa[2][3] += a.z * b.w;
                fa[3][0] += a.w * b.x; fa[3][1] += a.w * b.y; fa[3][2] += a.w * b.z; fa[3][3] += a.w * b.w;
            }
            const float sc = 0.17677669529663687f;
#pragma unroll
            for (int i = 0; i < 4; i++)
#pragma unroll
                for (int j = 0; j < 4; j++)
                    sm.Ss[tyA * 4 + i][txA * 4 + j] = fa[i][j] * sc;
            __syncthreads();

            {
                const float* srow = &sm.Ss[rB][hB * 16];
                float mloc = -1e30f;
#pragma unroll
                for (int j = 0; j < 16; j++) mloc = fmaxf(mloc, srow[j]);
                mloc = fmaxf(mloc, __shfl_xor_sync(0xffffffffu, mloc, 1));
                mloc = fmaxf(mloc, __shfl_xor_sync(0xffffffffu, mloc, 2));
                float m_old = sm.Ms[rB];
                float m_new = fmaxf(m_old, mloc);
                float corr = __expf(m_old - m_new);
                float s = 0.f;
#pragma unroll
                for (int j = 0; j < 16; j++) {
                    float e = __expf(srow[j] - m_new);
                    sm.Pt[hB * 16 + j][rB] = e;
                    s += e;
                }
                s += __shfl_xor_sync(0xffffffffu, s, 1);
                s += __shfl_xor_sync(0xffffffffu, s, 2);
                if (hB == 0) {
                    sm.Ms[rB] = m_new;
                    sm.Ls[rB] = sm.Ls[rB] * corr + s;
                    sm.Cs[rB] = corr;
                }
            }
            __syncthreads();

            const float c0 = sm.Cs[tyC * 2];
            const float c1 = sm.Cs[tyC * 2 + 1];
#pragma unroll
            for (int j = 0; j < 4; j++) { O[0][j] *= c0; O[1][j] *= c1; }
#pragma unroll 8
            for (int mm = 0; mm < 64; mm++) {
                const float a0 = sm.Pt[mm][tyC * 2];
                const float a1 = sm.Pt[mm][tyC * 2 + 1];
                float4 b = *(const float4*)&sm.Vs[mm][txC * 4];
                O[0][0] += a0 * b.x; O[0][1] += a0 * b.y; O[0][2] += a0 * b.z; O[0][3] += a0 * b.w;
                O[1][0] += a1 * b.x; O[1][1] += a1 * b.y; O[1][2] += a1 * b.z; O[1][3] += a1 * b.w;
            }
        }

#pragma unroll
        for (int i = 0; i < 2; i++) {
            const int l = l0 + tyC * 2 + i;
            const float inv = 1.0f / sm.Ls[tyC * 2 + i];
            float out[4];
#pragma unroll
            for (int j = 0; j < 4; j++) out[j] = O[i][j] * inv;
            *(float4*)(aod + (size_t)l * 128 + h * 32 + txC * 4) = *(float4*)out;
        }
    } else {
        ClsSmem& sm = reinterpret_cast<AttnSmem*>(raw)->c;
        const int idx = bx - 48;
        const int k = idx % 15 + 1;
        const int h = idx / 15;

#pragma unroll
        for (int t = 0; t < 3; t++) {
            const int f = tid + t * 256;
            const int r = f >> 3, c = (f & 7) * 4;
            const int b = r >> 1, cc = r & 1;
            const int j = cc ? (k - 1) : k;
            const float* base = qkvd + (size_t)(768 + b * 16 + j) * QKVW + h * 32 + c;
            *(float4*)&sm.Qc[r][c] = *(const float4*)(base);
            *(float4*)&sm.Kc[r][c] = *(const float4*)(base + 128);
            *(float4*)&sm.Vc[r][c] = *(const float4*)(base + 256);
        }
        __syncthreads();

        const int tx = tid & 15, ty = tid >> 4;
        {
            float acc[6][6];
#pragma unroll
            for (int i = 0; i < 6; i++)
#pragma unroll
                for (int j = 0; j < 6; j++) acc[i][j] = 0.f;
#pragma unroll 8
            for (int d = 0; d < 32; d++) {
                float a[6], b[6];
#pragma unroll
                for (int i = 0; i < 6; i++) a[i] = sm.Qc[ty * 6 + i][d];
#pragma unroll
                for (int j = 0; j < 6; j++) b[j] = sm.Kc[tx * 6 + j][d];
#pragma unroll
                for (int i = 0; i < 6; i++)
#pragma unroll
                    for (int j = 0; j < 6; j++) acc[i][j] += a[i] * b[j];
            }
            const float scl = 0.17677669529663687f;
#pragma unroll
            for (int i = 0; i < 6; i++)
#pragma unroll
                for (int j = 0; j < 6; j++)
                    sm.Sc[ty * 6 + i][tx * 6 + j] = acc[i][j] * scl;
        }
        __syncthreads();

        if (tid < 96) {
            float mx = -1e30f;
#pragma unroll 8
            for (int m = 0; m < 96; m++) mx = fmaxf(mx, sm.Sc[tid][m]);
            const float w0 = (float)k, w1 = (float)(16 - k);
            float s = 0.f;
#pragma unroll 8
            for (int m = 0; m < 96; m++) {
                float w = (m & 1) ? w1 : w0;
                float e = w * __expf(sm.Sc[tid][m] - mx);
                sm.Sc[tid][m] = e;
                s += e;
            }
            const float inv = 1.0f / s;
#pragma unroll 8
            for (int m = 0; m < 96; m++) sm.Sc[tid][m] *= inv;
        }
        __syncthreads();

        const int txo = tid & 7, tyo = tid >> 3;
        float o[3][4];
#pragma unroll
        for (int i = 0; i < 3; i++)
#pragma unroll
            for (int j = 0; j < 4; j++) o[i][j] = 0.f;
#pragma unroll 8
        for (int m = 0; m < 96; m++) {
            float a[3];
#pragma unroll
            for (int i = 0; i < 3; i++) a[i] = sm.Sc[tyo * 3 + i][m];
            float4 b = *(const float4*)&sm.Vc[m][txo * 4];
#pragma unroll
            for (int i = 0; i < 3; i++) {
                o[i][0] += a[i] * b.x; o[i][1] += a[i] * b.y;
                o[i][2] += a[i] * b.z; o[i][3] += a[i] * b.w;
            }
        }
#pragma unroll
        for (int i = 0; i < 3; i++) {
            const int row = 768 + (k - 1) * 96 + tyo * 3 + i;
            *(float4*)(aod + (size_t)row * 128 + h * 32 + txo * 4) = *(float4*)&o[i][0];
        }
    }
}

// ============================================================================
// K4: fused back chain. 70 CTAs x 32 rows over 2240.
// aop = ao@mow^T + mob + x1d[res_map]; ctx = relu(aop@roww^T + rob);
// qvd = ctx . qw + qb  (ctx/aop never hit gmem)
// ============================================================================
struct BackSmem {
    float At[128][33];
    float Pt[128][33];
    float Ws[2][16][64];
};

__global__ void __launch_bounds__(256)
fused_back(const float* __restrict__ aod, const float* __restrict__ x1d,
           const float* __restrict__ mow, const float* __restrict__ mob,
           const float* __restrict__ roww, const float* __restrict__ rob,
           const float* __restrict__ qw, const float* __restrict__ qb,
           float* __restrict__ qvd)
{
    extern __shared__ char raw[];
    BackSmem& sm = *reinterpret_cast<BackSmem*>(raw);
    const int tid = threadIdx.x;
    const int tx = tid & 15, ty = tid >> 4;
    const int lr = tid >> 2;
    const int row0 = blockIdx.x * 32;

    load_rows_t(aod, row0, 128, sm.At);

    int rm[2];
#pragma unroll
    for (int i = 0; i < 2; i++) rm[i] = res_map(row0 + ty * 2 + i);

    // stage 1: out_proj + gathered residual -> Pt
    for (int c = 0; c < 2; c++) {
        const float* wrow = mow + (size_t)(c * 64 + lr) * 128;
        float acc[2][4];
        chunk_gemm(sm.At, wrow, 128, sm.Ws, acc);
#pragma unroll
        for (int i = 0; i < 2; i++) {
            const int r = ty * 2 + i;
            float4 res = *(const float4*)(x1d + (size_t)rm[i] * 128 + c * 64 + tx * 4);
#pragma unroll
            for (int j = 0; j < 4; j++) {
                const int n = c * 64 + tx * 4 + j;
                const float rv = (j == 0) ? res.x : (j == 1) ? res.y : (j == 2) ? res.z : res.w;
                sm.Pt[n][r] = acc[i][j] + mob[n] + rv;
            }
        }
    }

    // stage 2: relu output layer, fused q-head dot product
    float qacc[2] = {0.f, 0.f};
    for (int c = 0; c < 2; c++) {
        const float* wrow = roww + (size_t)(c * 64 + lr) * 128;
        float acc[2][4];
        chunk_gemm(sm.Pt, wrow, 128, sm.Ws, acc);
        float4 qv4 = *(const float4*)(qw + c * 64 + tx * 4);
#pragma unroll
        for (int i = 0; i < 2; i++) {
#pragma unroll
            for (int j = 0; j < 4; j++) {
                const int n = c * 64 + tx * 4 + j;
                const float v = fmaxf(acc[i][j] + rob[n], 0.f);
                const float qwv = (j == 0) ? qv4.x : (j == 1) ? qv4.y : (j == 2) ? qv4.z : qv4.w;
                qacc[i] += v * qwv;
            }
        }
    }
    // reduce across the 16 threads (tx) sharing each row
#pragma unroll
    for (int i = 0; i < 2; i++) {
        float s = qacc[i];
#pragma unroll
        for (int off = 8; off; off >>= 1) s += __shfl_xor_sync(0xffffffffu, s, off);
        const int grow = row0 + ty * 2 + i;
        if (tx == 0 && grow < 2208) qvd[grow] = s + qb[0];
    }
}

// ---- assemble q_values from class values ----
__global__ void assemble(const float* __restrict__ qvd, float* __restrict__ out_q)
{
    const int l = blockIdx.x * 256 + threadIdx.x;
    if (l >= 768) return;
    const int b = l >> 4, i = l & 15;
    float s = qvd[l];
#pragma unroll
    for (int k = 1; k < 16; k++) {
        const int c = (i < k) ? 0 : 1;
        s += qvd[768 + (k - 1) * 96 + b * 2 + c];
    }
    out_q[l] = s;
}

extern "C" void kernel_launch(void* const* d_in, const int* in_sizes, int n_in,
                              void* d_out, int out_size)
{
    const float* obs = (const float*)d_in[0];
    const float* aw1 = (const float*)d_in[1];  const float* ab1 = (const float*)d_in[2];
    const float* aw2 = (const float*)d_in[3];  const float* ab2 = (const float*)d_in[4];
    const float* aw3 = (const float*)d_in[5];  const float* ab3 = (const float*)d_in[6];
    const float* eow = (const float*)d_in[7];  const float* eob = (const float*)d_in[8];
    const float* eaw = (const float*)d_in[9];  const float* eab = (const float*)d_in[10];
    const float* riw = (const float*)d_in[11]; const float* rib = (const float*)d_in[12];
    const float* roww = (const float*)d_in[13]; const float* rob = (const float*)d_in[14];
    const float* miw = (const float*)d_in[15]; const float* mib = (const float*)d_in[16];
    const float* mow = (const float*)d_in[17]; const float* mob = (const float*)d_in[18];
    const float* qw  = (const float*)d_in[19]; const float* qb  = (const float*)d_in[20];

    float* out = (float*)d_out;
    float* out_policy = out + OUT_POLICY;
    float* out_q      = out + OUT_Q;
    float* out_eo     = out + OUT_EO;

    float *eoea, *x1d, *qkvd, *aod, *qvd;
    cudaGetSymbolAddress((void**)&eoea, g_eoea);
    cudaGetSymbolAddress((void**)&x1d, g_x1d);
    cudaGetSymbolAddress((void**)&qkvd, g_qkvd);
    cudaGetSymbolAddress((void**)&aod, g_aod);
    cudaGetSymbolAddress((void**)&qvd, g_qvd);

    cudaFuncSetAttribute(fused_front, cudaFuncAttributeMaxDynamicSharedMemorySize,
                         (int)sizeof(FrontSmem));
    cudaFuncSetAttribute(fused_mid, cudaFuncAttributeMaxDynamicSharedMemorySize,
                         (int)sizeof(MidSmem));
    cudaFuncSetAttribute(attn_combined, cudaFuncAttributeMaxDynamicSharedMemorySize,
                         (int)sizeof(AttnSmem));
    cudaFuncSetAttribute(fused_back, cudaFuncAttributeMaxDynamicSharedMemorySize,
                         (int)sizeof(BackSmem));

    fused_front<<<24, 256, sizeof(FrontSmem)>>>(obs, aw1, ab1, aw2, ab2, aw3, ab3,
                                                eow, eob, eaw, eab,
                                                out_eo, out_policy, eoea);
    fused_mid<<<48, 256, sizeof(MidSmem)>>>(eoea, riw, rib, miw, mib, x1d, qkvd);
    attn_combined<<<108, 256, sizeof(AttnSmem)>>>(qkvd, aod);
    fused_back<<<70, 256, sizeof(BackSmem)>>>(aod, x1d, mow, mob, roww, rob, qw, qb, qvd);
    assemble<<<3, 256>>>(qvd, out_q);

    (void)in_sizes; (void)n_in; (void)out_size;
}

// round 5
// speedup vs baseline: 1.5434x; 1.5434x over previous
#include <cuda_runtime.h>
#include <math.h>

// ---- problem dims ----
#define NB 48
#define NA 16
#define LL 768            // NB*NA
#define EMB 128
#define QKVW 384
#define MPOST 2240        // 2208 valid rows padded to 35*64

// output layout in d_out (floats): policy_flat | q_values | eo
#define OUT_POLICY 0
#define OUT_Q      24576
#define OUT_EO     25344

// ---- scratch ----
__device__ __align__(256) float g_H1[LL * 256];
__device__ __align__(256) float g_H2[LL * 128];
__device__ __align__(256) float g_eoea[1536 * 128];
__device__ __align__(256) float g_x1d[1536 * 128];
__device__ __align__(256) float g_qkvd[1536 * QKVW];
__device__ __align__(256) float g_aod[MPOST * 128];   // zero-init: pad rows stay 0
__device__ __align__(256) float g_aopd[MPOST * 128];
__device__ __align__(256) float g_ctxd[MPOST * 128];
__device__ __align__(256) float g_qvd[MPOST];
// flash split-m partials
__device__ __align__(256) float g_fO[2 * 4 * LL * 32];
__device__ __align__(256) float g_fM[2 * 4 * LL];
__device__ __align__(256) float g_fL[2 * 4 * LL];

#define ACT_NONE 0
#define ACT_LEAKY 1
#define ACT_GELU 2
#define ACT_RELU 3

__device__ __forceinline__ int res_map(int m) {
    if (m < 768) return m;
    int t = m - 768;
    if (t >= 1440) return 0;
    int k = t / 96 + 1;
    int r = t % 96;
    int b = r >> 1, c = r & 1;
    int j = c ? (k - 1) : k;
    return 768 + b * 16 + j;
}

// ============================================================================
// gemm64db: 64x64x16, 4x4 micro, double-buffered (R3-proven, unchanged).
// ============================================================================
template <int ACTI, bool CATA, bool SPLIT, bool RESG>
__global__ void __launch_bounds__(256)
gemm64db(const float* __restrict__ A, const float* __restrict__ A2,
         const float* __restrict__ W, const float* __restrict__ W2,
         const float* __restrict__ bias, const float* __restrict__ bias2,
         const float* __restrict__ Res,
         float* __restrict__ C, float* __restrict__ C2, float* __restrict__ C3,
         int M, int N, int K)
{
    __shared__ __align__(16) float As[2][16][64];
    __shared__ __align__(16) float Ws[2][16][64];

    const int tid = threadIdx.x;
    const int tx = tid & 15;
    const int ty = tid >> 4;
    const int m0 = blockIdx.y * 64;
    const int n0 = blockIdx.x * 64;
    const int lr = tid >> 2;
    const int lc = (tid & 3) * 4;

    auto loadA = [&](int k0) -> float4 {
        const int k = k0 + lc;
        if (CATA) {
            const float* p = (k < 128) ? (A  + (size_t)(m0 + lr) * 128 + k)
                                       : (A2 + (size_t)(m0 + lr) * 32 + (k - 128));
            return *(const float4*)p;
        }
        return *(const float4*)(A + (size_t)(m0 + lr) * K + k);
    };
    auto loadW = [&](int k0) -> float4 {
        const int n = n0 + lr;
        if (SPLIT) {
            const float* p = (n < 256) ? (W  + (size_t)n * K + k0 + lc)
                                       : (W2 + (size_t)(n - 256) * K + k0 + lc);
            return *(const float4*)p;
        }
        if (n < N) return *(const float4*)(W + (size_t)n * K + k0 + lc);
        return make_float4(0.f, 0.f, 0.f, 0.f);
    };

    float acc[4][4];
#pragma unroll
    for (int i = 0; i < 4; i++)
#pragma unroll
        for (int j = 0; j < 4; j++) acc[i][j] = 0.f;

    float4 a_pre = loadA(0);
    float4 w_pre = loadW(0);
    As[0][lc + 0][lr] = a_pre.x; As[0][lc + 1][lr] = a_pre.y;
    As[0][lc + 2][lr] = a_pre.z; As[0][lc + 3][lr] = a_pre.w;
    Ws[0][lc + 0][lr] = w_pre.x; Ws[0][lc + 1][lr] = w_pre.y;
    Ws[0][lc + 2][lr] = w_pre.z; Ws[0][lc + 3][lr] = w_pre.w;
    __syncthreads();

    int buf = 0;
    for (int k0 = 0; k0 < K; k0 += 16) {
        const bool has_next = (k0 + 16 < K);
        if (has_next) { a_pre = loadA(k0 + 16); w_pre = loadW(k0 + 16); }
#pragma unroll
        for (int kk = 0; kk < 16; kk++) {
            float4 a = *(const float4*)&As[buf][kk][ty * 4];
            float4 b = *(const float4*)&Ws[buf][kk][tx * 4];
            acc[0][0] += a.x * b.x; acc[0][1] += a.x * b.y; acc[0][2] += a.x * b.z; acc[0][3] += a.x * b.w;
            acc[1][0] += a.y * b.x; acc[1][1] += a.y * b.y; acc[1][2] += a.y * b.z; acc[1][3] += a.y * b.w;
            acc[2][0] += a.z * b.x; acc[2][1] += a.z * b.y; acc[2][2] += a.z * b.z; acc[2][3] += a.z * b.w;
            acc[3][0] += a.w * b.x; acc[3][1] += a.w * b.y; acc[3][2] += a.w * b.z; acc[3][3] += a.w * b.w;
        }
        if (has_next) {
            const int nb = buf ^ 1;
            As[nb][lc + 0][lr] = a_pre.x; As[nb][lc + 1][lr] = a_pre.y;
            As[nb][lc + 2][lr] = a_pre.z; As[nb][lc + 3][lr] = a_pre.w;
            Ws[nb][lc + 0][lr] = w_pre.x; Ws[nb][lc + 1][lr] = w_pre.y;
            Ws[nb][lc + 2][lr] = w_pre.z; Ws[nb][lc + 3][lr] = w_pre.w;
            __syncthreads();
            buf = nb;
        }
    }

#pragma unroll
    for (int i = 0; i < 4; i++) {
        const int m = m0 + ty * 4 + i;
        const float* rres = nullptr;
        if (RESG) rres = Res + (size_t)res_map(m) * 128;
#pragma unroll
        for (int j = 0; j < 4; j++) {
            const int n = n0 + tx * 4 + j;
            if (SPLIT) {
                if (n < 256) {
                    float v = acc[i][j] + bias[n];
                    v = (v > 0.f) ? v : 0.01f * v;
                    C[(size_t)m * 256 + n] = v;
                } else {
                    float v = acc[i][j] + bias2[n - 256];
                    C2[(size_t)m * 128 + (n - 256)] = v;
                    C3[(size_t)m * 128 + (n - 256)] = v;
                }
            } else if (n < N) {
                float v = acc[i][j] + bias[n];
                if (RESG) v += rres[n];
                if (ACTI == ACT_LEAKY) v = (v > 0.f) ? v : 0.01f * v;
                else if (ACTI == ACT_GELU) v = 0.5f * v * (1.0f + erff(v * 0.70710678118654752f));
                else if (ACTI == ACT_RELU) v = fmaxf(v, 0.f);
                C[(size_t)m * N + n] = v;
            }
        }
    }
}

// ============================================================================
// combined attention: blocks 0..95 flash split-m partials, 96..155 class attn
// ============================================================================
struct Flash64Smem {
    float Qs[32][68];
    float Ks[32][68];
    float Vs[64][36];
    float Ss[64][68];
    float Pt[64][68];
    float Ms[64], Ls[64], Cs[64];
};
struct ClsSmem {
    float Qc[96][36];
    float Kc[96][36];
    float Vc[96][36];
    float Sc[96][97];
};
union AttnSmem { Flash64Smem f; ClsSmem c; };

__global__ void __launch_bounds__(256)
attn_combined(const float* __restrict__ qkvd, float* __restrict__ aod,
              float* __restrict__ fO, float* __restrict__ fM, float* __restrict__ fL)
{
    extern __shared__ char raw[];
    const int bx = blockIdx.x;
    const int tid = threadIdx.x;

    if (bx < 96) {
        Flash64Smem& sm = reinterpret_cast<AttnSmem*>(raw)->f;
        const int half = bx / 48;
        const int rem = bx % 48;
        const int h = rem / 12;
        const int l0 = (rem % 12) * 64;
        const float* Qb = qkvd + h * 32;
        const float* Kb = qkvd + 128 + h * 32;
        const float* Vb = qkvd + 256 + h * 32;

#pragma unroll
        for (int t = 0; t < 2; t++) {
            const int f = tid + t * 256;
            const int r = f >> 3, c = (f & 7) * 4;
            float4 v = *(const float4*)(Qb + (size_t)(l0 + r) * QKVW + c);
            sm.Qs[c + 0][r] = v.x; sm.Qs[c + 1][r] = v.y;
            sm.Qs[c + 2][r] = v.z; sm.Qs[c + 3][r] = v.w;
        }
        if (tid < 64) { sm.Ms[tid] = -1e30f; sm.Ls[tid] = 0.f; }

        float O[2][4];
#pragma unroll
        for (int i = 0; i < 2; i++)
#pragma unroll
            for (int j = 0; j < 4; j++) O[i][j] = 0.f;

        const int txA = tid & 15, tyA = tid >> 4;
        const int rB = tid >> 2,  hB = tid & 3;
        const int txC = tid & 7,  tyC = tid >> 3;

        const int mbeg = half * 384;
        for (int m0 = mbeg; m0 < mbeg + 384; m0 += 64) {
            __syncthreads();
#pragma unroll
            for (int t = 0; t < 2; t++) {
                const int f = tid + t * 256;
                const int r = f >> 3, c = (f & 7) * 4;
                float4 kv = *(const float4*)(Kb + (size_t)(m0 + r) * QKVW + c);
                sm.Ks[c + 0][r] = kv.x; sm.Ks[c + 1][r] = kv.y;
                sm.Ks[c + 2][r] = kv.z; sm.Ks[c + 3][r] = kv.w;
                float4 vv = *(const float4*)(Vb + (size_t)(m0 + r) * QKVW + c);
                *(float4*)&sm.Vs[r][c] = vv;
            }
            __syncthreads();

            float fa[4][4];
#pragma unroll
            for (int i = 0; i < 4; i++)
#pragma unroll
                for (int j = 0; j < 4; j++) fa[i][j] = 0.f;
#pragma unroll 8
            for (int d = 0; d < 32; d++) {
                float4 a = *(const float4*)&sm.Qs[d][tyA * 4];
                float4 b = *(const float4*)&sm.Ks[d][txA * 4];
                fa[0][0] += a.x * b.x; fa[0][1] += a.x * b.y; fa[0][2] += a.x * b.z; fa[0][3] += a.x * b.w;
                fa[1][0] += a.y * b.x; fa[1][1] += a.y * b.y; fa[1][2] += a.y * b.z; fa[1][3] += a.y * b.w;
                fa[2][0] += a.z * b.x; fa[2][1] += a.z * b.y; fa[2][2] += a.z * b.z; fa[2][3] += a.z * b.w;
                fa[3][0] += a.w * b.x; fa[3][1] += a.w * b.y; fa[3][2] += a.w * b.z; fa[3][3] += a.w * b.w;
            }
            const float sc = 0.17677669529663687f;
#pragma unroll
            for (int i = 0; i < 4; i++)
#pragma unroll
                for (int j = 0; j < 4; j++)
                    sm.Ss[tyA * 4 + i][txA * 4 + j] = fa[i][j] * sc;
            __syncthreads();

            {
                const float* srow = &sm.Ss[rB][hB * 16];
                float mloc = -1e30f;
#pragma unroll
                for (int j = 0; j < 16; j++) mloc = fmaxf(mloc, srow[j]);
                mloc = fmaxf(mloc, __shfl_xor_sync(0xffffffffu, mloc, 1));
                mloc = fmaxf(mloc, __shfl_xor_sync(0xffffffffu, mloc, 2));
                float m_old = sm.Ms[rB];
                float m_new = fmaxf(m_old, mloc);
                float corr = __expf(m_old - m_new);
                float s = 0.f;
#pragma unroll
                for (int j = 0; j < 16; j++) {
                    float e = __expf(srow[j] - m_new);
                    sm.Pt[hB * 16 + j][rB] = e;
                    s += e;
                }
                s += __shfl_xor_sync(0xffffffffu, s, 1);
                s += __shfl_xor_sync(0xffffffffu, s, 2);
                if (hB == 0) {
                    sm.Ms[rB] = m_new;
                    sm.Ls[rB] = sm.Ls[rB] * corr + s;
                    sm.Cs[rB] = corr;
                }
            }
            __syncthreads();

            const float c0 = sm.Cs[tyC * 2];
            const float c1 = sm.Cs[tyC * 2 + 1];
#pragma unroll
            for (int j = 0; j < 4; j++) { O[0][j] *= c0; O[1][j] *= c1; }
#pragma unroll 8
            for (int mm = 0; mm < 64; mm++) {
                const float a0 = sm.Pt[mm][tyC * 2];
                const float a1 = sm.Pt[mm][tyC * 2 + 1];
                float4 b = *(const float4*)&sm.Vs[mm][txC * 4];
                O[0][0] += a0 * b.x; O[0][1] += a0 * b.y; O[0][2] += a0 * b.z; O[0][3] += a0 * b.w;
                O[1][0] += a1 * b.x; O[1][1] += a1 * b.y; O[1][2] += a1 * b.z; O[1][3] += a1 * b.w;
            }
        }

        const int pb = half * 4 + h;
#pragma unroll
        for (int i = 0; i < 2; i++) {
            const int r = tyC * 2 + i;
            const int l = l0 + r;
            *(float4*)(fO + ((size_t)pb * LL + l) * 32 + txC * 4) = *(float4*)&O[i][0];
            if (txC == 0) {
                fM[(size_t)pb * LL + l] = sm.Ms[r];
                fL[(size_t)pb * LL + l] = sm.Ls[r];
            }
        }
    } else {
        ClsSmem& sm = reinterpret_cast<AttnSmem*>(raw)->c;
        const int idx = bx - 96;
        const int k = idx % 15 + 1;
        const int h = idx / 15;

#pragma unroll
        for (int t = 0; t < 3; t++) {
            const int f = tid + t * 256;
            const int r = f >> 3, c = (f & 7) * 4;
            const int b = r >> 1, cc = r & 1;
            const int j = cc ? (k - 1) : k;
            const float* base = qkvd + (size_t)(768 + b * 16 + j) * QKVW + h * 32 + c;
            *(float4*)&sm.Qc[r][c] = *(const float4*)(base);
            *(float4*)&sm.Kc[r][c] = *(const float4*)(base + 128);
            *(float4*)&sm.Vc[r][c] = *(const float4*)(base + 256);
        }
        __syncthreads();

        const int tx = tid & 15, ty = tid >> 4;
        {
            float acc[6][6];
#pragma unroll
            for (int i = 0; i < 6; i++)
#pragma unroll
                for (int j = 0; j < 6; j++) acc[i][j] = 0.f;
#pragma unroll 8
            for (int d = 0; d < 32; d++) {
                float a[6], b[6];
#pragma unroll
                for (int i = 0; i < 6; i++) a[i] = sm.Qc[ty * 6 + i][d];
#pragma unroll
                for (int j = 0; j < 6; j++) b[j] = sm.Kc[tx * 6 + j][d];
#pragma unroll
                for (int i = 0; i < 6; i++)
#pragma unroll
                    for (int j = 0; j < 6; j++) acc[i][j] += a[i] * b[j];
            }
            const float scl = 0.17677669529663687f;
#pragma unroll
            for (int i = 0; i < 6; i++)
#pragma unroll
                for (int j = 0; j < 6; j++)
                    sm.Sc[ty * 6 + i][tx * 6 + j] = acc[i][j] * scl;
        }
        __syncthreads();

        if (tid < 96) {
            float mx = -1e30f;
#pragma unroll 8
            for (int m = 0; m < 96; m++) mx = fmaxf(mx, sm.Sc[tid][m]);
            const float w0 = (float)k, w1 = (float)(16 - k);
            float s = 0.f;
#pragma unroll 8
            for (int m = 0; m < 96; m++) {
                float w = (m & 1) ? w1 : w0;
                float e = w * __expf(sm.Sc[tid][m] - mx);
                sm.Sc[tid][m] = e;
                s += e;
            }
            const float inv = 1.0f / s;
#pragma unroll 8
            for (int m = 0; m < 96; m++) sm.Sc[tid][m] *= inv;
        }
        __syncthreads();

        const int txo = tid & 7, tyo = tid >> 3;
        float o[3][4];
#pragma unroll
        for (int i = 0; i < 3; i++)
#pragma unroll
            for (int j = 0; j < 4; j++) o[i][j] = 0.f;
#pragma unroll 8
        for (int m = 0; m < 96; m++) {
            float a[3];
#pragma unroll
            for (int i = 0; i < 3; i++) a[i] = sm.Sc[tyo * 3 + i][m];
            float4 b = *(const float4*)&sm.Vc[m][txo * 4];
#pragma unroll
            for (int i = 0; i < 3; i++) {
                o[i][0] += a[i] * b.x; o[i][1] += a[i] * b.y;
                o[i][2] += a[i] * b.z; o[i][3] += a[i] * b.w;
            }
        }
#pragma unroll
        for (int i = 0; i < 3; i++) {
            const int row = 768 + (k - 1) * 96 + tyo * 3 + i;
            *(float4*)(aod + (size_t)row * 128 + h * 32 + txo * 4) = *(float4*)&o[i][0];
        }
    }
}

// ---- combine flash halves (exact log-sum-exp merge) ----
__global__ void __launch_bounds__(256)
attn_combine(const float* __restrict__ fO, const float* __restrict__ fM,
             const float* __restrict__ fL, float* __restrict__ aod)
{
    const int g = blockIdx.x * 256 + threadIdx.x;   // 0..24575
    const int pair = g >> 3;                         // h*768 + l
    const int lane = g & 7;
    const int h = pair / LL, l = pair % LL;
    const int i1 = h * LL + l;
    const int i2 = (4 + h) * LL + l;
    const float m1 = fM[i1], m2 = fM[i2];
    const float M = fmaxf(m1, m2);
    const float w1 = __expf(m1 - M), w2 = __expf(m2 - M);
    const float inv = 1.0f / (w1 * fL[i1] + w2 * fL[i2]);
    const float4 o1 = *(const float4*)(fO + (size_t)i1 * 32 + lane * 4);
    const float4 o2 = *(const float4*)(fO + (size_t)i2 * 32 + lane * 4);
    float4 o;
    o.x = (w1 * o1.x + w2 * o2.x) * inv;
    o.y = (w1 * o1.y + w2 * o2.y) * inv;
    o.z = (w1 * o1.z + w2 * o2.z) * inv;
    o.w = (w1 * o1.w + w2 * o2.w) * inv;
    *(float4*)(aod + (size_t)l * 128 + h * 32 + lane * 4) = o;
}

// ---- per-row q scalar ----
__global__ void qv_rows(const float* __restrict__ ctx, const float* __restrict__ qw,
                        const float* __restrict__ qb, float* __restrict__ qvd)
{
    const int w = (blockIdx.x * blockDim.x + threadIdx.x) >> 5;
    const int lane = threadIdx.x & 31;
    if (w >= 2208) return;
    const float* r = ctx + (size_t)w * 128;
    float s = 0.f;
#pragma unroll
    for (int c = lane; c < 128; c += 32) s += r[c] * qw[c];
#pragma unroll
    for (int o = 16; o; o >>= 1) s += __shfl_xor_sync(0xffffffffu, s, o);
    if (!lane) qvd[w] = s + qb[0];
}

// ---- assemble q_values from class values ----
__global__ void assemble(const float* __restrict__ qvd, float* __restrict__ out_q)
{
    const int l = blockIdx.x * 256 + threadIdx.x;
    if (l >= 768) return;
    const int b = l >> 4, i = l & 15;
    float s = qvd[l];
#pragma unroll
    for (int k = 1; k < 16; k++) {
        const int c = (i < k) ? 0 : 1;
        s += qvd[768 + (k - 1) * 96 + b * 2 + c];
    }
    out_q[l] = s;
}

extern "C" void kernel_launch(void* const* d_in, const int* in_sizes, int n_in,
                              void* d_out, int out_size)
{
    const float* obs = (const float*)d_in[0];
    const float* aw1 = (const float*)d_in[1];  const float* ab1 = (const float*)d_in[2];
    const float* aw2 = (const float*)d_in[3];  const float* ab2 = (const float*)d_in[4];
    const float* aw3 = (const float*)d_in[5];  const float* ab3 = (const float*)d_in[6];
    const float* eow = (const float*)d_in[7];  const float* eob = (const float*)d_in[8];
    const float* eaw = (const float*)d_in[9];  const float* eab = (const float*)d_in[10];
    const float* riw = (const float*)d_in[11]; const float* rib = (const float*)d_in[12];
    const float* roww = (const float*)d_in[13]; const float* rob = (const float*)d_in[14];
    const float* miw = (const float*)d_in[15]; const float* mib = (const float*)d_in[16];
    const float* mow = (const float*)d_in[17]; const float* mob = (const float*)d_in[18];
    const float* qw  = (const float*)d_in[19]; const float* qb  = (const float*)d_in[20];

    float* out = (float*)d_out;
    float* out_policy = out + OUT_POLICY;
    float* out_q      = out + OUT_Q;
    float* out_eo     = out + OUT_EO;

    float *H1, *H2, *eoea, *x1d, *qkvd, *aod, *aopd, *ctxd, *qvd, *fO, *fM, *fL;
    cudaGetSymbolAddress((void**)&H1, g_H1);
    cudaGetSymbolAddress((void**)&H2, g_H2);
    cudaGetSymbolAddress((void**)&eoea, g_eoea);
    cudaGetSymbolAddress((void**)&x1d, g_x1d);
    cudaGetSymbolAddress((void**)&qkvd, g_qkvd);
    cudaGetSymbolAddress((void**)&aod, g_aod);
    cudaGetSymbolAddress((void**)&aopd, g_aopd);
    cudaGetSymbolAddress((void**)&ctxd, g_ctxd);
    cudaGetSymbolAddress((void**)&qvd, g_qvd);
    cudaGetSymbolAddress((void**)&fO, g_fO);
    cudaGetSymbolAddress((void**)&fM, g_fM);
    cudaGetSymbolAddress((void**)&fL, g_fL);

    cudaFuncSetAttribute(attn_combined, cudaFuncAttributeMaxDynamicSharedMemorySize,
                         (int)sizeof(AttnSmem));

    dim3 blk(256);

    gemm64db<ACT_NONE, false, true, false><<<dim3(6, 12), blk>>>(
        obs, nullptr, aw1, eow, ab1, eob, nullptr, H1, out_eo, eoea, LL, 384, 128);
    gemm64db<ACT_LEAKY, false, false, false><<<dim3(2, 12), blk>>>(
        H1, nullptr, aw2, nullptr, ab2, nullptr, nullptr, H2, nullptr, nullptr, LL, 128, 256);
    gemm64db<ACT_GELU, false, false, false><<<dim3(1, 12), blk>>>(
        H2, nullptr, aw3, nullptr, ab3, nullptr, nullptr, out_policy, nullptr, nullptr, LL, 32, 128);
    gemm64db<ACT_NONE, true, false, false><<<dim3(2, 12), blk>>>(
        obs, out_policy, eaw, nullptr, eab, nullptr, nullptr, eoea + 768 * 128,
        nullptr, nullptr, LL, 128, 160);
    gemm64db<ACT_RELU, false, false, false><<<dim3(2, 24), blk>>>(
        eoea, nullptr, riw, nullptr, rib, nullptr, nullptr, x1d, nullptr, nullptr, 1536, 128, 128);
    gemm64db<ACT_NONE, false, false, false><<<dim3(6, 24), blk>>>(
        x1d, nullptr, miw, nullptr, mib, nullptr, nullptr, qkvd, nullptr, nullptr, 1536, 384, 128);

    attn_combined<<<156, blk, sizeof(AttnSmem)>>>(qkvd, aod, fO, fM, fL);
    attn_combine<<<96, blk>>>(fO, fM, fL, aod);

    gemm64db<ACT_NONE, false, false, true><<<dim3(2, 35), blk>>>(
        aod, nullptr, mow, nullptr, mob, nullptr, x1d, aopd, nullptr, nullptr, MPOST, 128, 128);
    gemm64db<ACT_RELU, false, false, false><<<dim3(2, 35), blk>>>(
        aopd, nullptr, roww, nullptr, rob, nullptr, nullptr, ctxd, nullptr, nullptr, MPOST, 128, 128);

    qv_rows<<<(2208 * 32 + 255) / 256, blk>>>(ctxd, qw, qb, qvd);
    assemble<<<3, 256>>>(qvd, out_q);

    (void)in_sizes; (void)n_in; (void)out_size;
}

// round 6
// speedup vs baseline: 1.9157x; 1.2412x over previous
#include <cuda_runtime.h>
#include <math.h>

// ---- problem dims ----
#define NB 48
#define NA 16
#define LL 768            // NB*NA
#define EMB 128
#define QKVW 384
#define MPOST 2240        // 2208 valid rows padded to 70*32

// output layout in d_out (floats): policy_flat | q_values | eo
#define OUT_POLICY 0
#define OUT_Q      24576
#define OUT_EO     25344

// ---- scratch ----
__device__ __align__(256) float g_H1[LL * 256];
__device__ __align__(256) float g_H2[LL * 128];
__device__ __align__(256) float g_eoea[1536 * 128];
__device__ __align__(256) float g_x1d[1536 * 128];
__device__ __align__(256) float g_qkvd[1536 * QKVW];
__device__ __align__(256) float g_aod[MPOST * 128];   // rows 768.. written by cls_attn; pads stay 0
__device__ __align__(256) float g_aopd[MPOST * 128];
__device__ __align__(256) float g_qvp[2 * MPOST];     // q-head partials (n-halves)
// flash split-m partials
__device__ __align__(256) float g_fO[2 * 4 * LL * 32];
__device__ __align__(256) float g_fM[2 * 4 * LL];
__device__ __align__(256) float g_fL[2 * 4 * LL];

#define ACT_NONE 0
#define ACT_LEAKY 1
#define ACT_GELU 2
#define ACT_RELU 3

__device__ __forceinline__ int res_map(int m) {
    if (m < 768) return m;
    int t = m - 768;
    if (t >= 1440) return 0;
    int k = t / 96 + 1;
    int r = t % 96;
    int b = r >> 1, c = r & 1;
    int j = c ? (k - 1) : k;
    return 768 + b * 16 + j;
}

// ============================================================================
// gemm32: 32x64xK tiles, 256 threads, micro 2m x 4n, double-buffered.
//   SPLIT  : G1 (N=384: aw1 rows<256 -> leaky -> C stride 256; else eow -> C2&C3)
//   RESG   : + Res[res_map(m)] in epilogue
//   COMBINE: rows m<768 of A come from flash partials fO/fM/fL (log-sum-exp merge)
//   QHEAD  : epilogue computes dot(row, qwv) partial -> qvp[bx*MPOST+m]; no C write
// ============================================================================
template <int ACTI, bool SPLIT, bool RESG, bool COMBINE, bool QHEAD>
__global__ void __launch_bounds__(256)
gemm32(const float* __restrict__ A,
       const float* __restrict__ W, const float* __restrict__ W2,
       const float* __restrict__ bias, const float* __restrict__ bias2,
       const float* __restrict__ Res,
       const float* __restrict__ fO, const float* __restrict__ fM,
       const float* __restrict__ fL,
       const float* __restrict__ qwv, float* __restrict__ qvp,
       float* __restrict__ C, float* __restrict__ C2, float* __restrict__ C3,
       int M, int N, int K)
{
    __shared__ __align__(16) float As[2][16][34];
    __shared__ __align__(16) float Ws[2][16][64];
    __shared__ float W1s[32][4], W2s[32][4];

    const int tid = threadIdx.x;
    const int tx = tid & 15, ty = tid >> 4;
    const int m0 = blockIdx.y * 32, n0 = blockIdx.x * 64;
    const int ar = tid >> 2;            // 0..63 (A uses tid<128 -> 0..31)
    const int ac = (tid & 3) * 4;

    const bool comb = COMBINE && (m0 < 768);
    if (COMBINE) {
        if (comb && tid < 128) {
            const int r = tid >> 2, h = tid & 3;
            const int i1 = h * LL + (m0 + r);
            const int i2 = (4 + h) * LL + (m0 + r);
            const float m1 = fM[i1], m2 = fM[i2];
            const float Mx = fmaxf(m1, m2);
            const float w1 = __expf(m1 - Mx), w2 = __expf(m2 - Mx);
            const float inv = 1.0f / (w1 * fL[i1] + w2 * fL[i2]);
            W1s[r][h] = w1 * inv;
            W2s[r][h] = w2 * inv;
        }
        __syncthreads();
    }

    auto loadA = [&](int k0) -> float4 {
        if (COMBINE && comb) {
            const int kc = k0 + ac;
            const int h = kc >> 5, d = kc & 31;
            const int l = m0 + ar;
            const float4 o1 = *(const float4*)(fO + ((size_t)h * LL + l) * 32 + d);
            const float4 o2 = *(const float4*)(fO + ((size_t)(4 + h) * LL + l) * 32 + d);
            const float w1 = W1s[ar][h], w2 = W2s[ar][h];
            return make_float4(w1 * o1.x + w2 * o2.x, w1 * o1.y + w2 * o2.y,
                               w1 * o1.z + w2 * o2.z, w1 * o1.w + w2 * o2.w);
        }
        return *(const float4*)(A + (size_t)(m0 + ar) * K + k0 + ac);
    };
    auto loadW = [&](int k0) -> float4 {
        const int n = n0 + ar;
        if (SPLIT) {
            const float* p = (n < 256) ? (W  + (size_t)n * K + k0 + ac)
                                       : (W2 + (size_t)(n - 256) * K + k0 + ac);
            return *(const float4*)p;
        }
        return *(const float4*)(W + (size_t)n * K + k0 + ac);
    };

    float acc[2][4];
#pragma unroll
    for (int i = 0; i < 2; i++)
#pragma unroll
        for (int j = 0; j < 4; j++) acc[i][j] = 0.f;

    float4 a_pre, w_pre;
    if (tid < 128) a_pre = loadA(0);
    w_pre = loadW(0);
    if (tid < 128) {
        As[0][ac + 0][ar] = a_pre.x; As[0][ac + 1][ar] = a_pre.y;
        As[0][ac + 2][ar] = a_pre.z; As[0][ac + 3][ar] = a_pre.w;
    }
    Ws[0][ac + 0][ar] = w_pre.x; Ws[0][ac + 1][ar] = w_pre.y;
    Ws[0][ac + 2][ar] = w_pre.z; Ws[0][ac + 3][ar] = w_pre.w;
    __syncthreads();

    int buf = 0;
    for (int k0 = 0; k0 < K; k0 += 16) {
        const bool has_next = (k0 + 16 < K);
        if (has_next) {
            if (tid < 128) a_pre = loadA(k0 + 16);
            w_pre = loadW(k0 + 16);
        }
#pragma unroll
        for (int kk = 0; kk < 16; kk++) {
            const float2 a = *(const float2*)&As[buf][kk][ty * 2];
            const float4 b = *(const float4*)&Ws[buf][kk][tx * 4];
            acc[0][0] += a.x * b.x; acc[0][1] += a.x * b.y;
            acc[0][2] += a.x * b.z; acc[0][3] += a.x * b.w;
            acc[1][0] += a.y * b.x; acc[1][1] += a.y * b.y;
            acc[1][2] += a.y * b.z; acc[1][3] += a.y * b.w;
        }
        if (has_next) {
            const int nb = buf ^ 1;
            if (tid < 128) {
                As[nb][ac + 0][ar] = a_pre.x; As[nb][ac + 1][ar] = a_pre.y;
                As[nb][ac + 2][ar] = a_pre.z; As[nb][ac + 3][ar] = a_pre.w;
            }
            Ws[nb][ac + 0][ar] = w_pre.x; Ws[nb][ac + 1][ar] = w_pre.y;
            Ws[nb][ac + 2][ar] = w_pre.z; Ws[nb][ac + 3][ar] = w_pre.w;
            __syncthreads();
            buf = nb;
        }
    }

    float qp[2] = {0.f, 0.f};
#pragma unroll
    for (int i = 0; i < 2; i++) {
        const int m = m0 + ty * 2 + i;
        const float* rres = nullptr;
        if (RESG) rres = Res + (size_t)res_map(m) * 128;
#pragma unroll
        for (int j = 0; j < 4; j++) {
            const int n = n0 + tx * 4 + j;
            if (SPLIT) {
                if (n < 256) {
                    float v = acc[i][j] + bias[n];
                    v = (v > 0.f) ? v : 0.01f * v;
                    C[(size_t)m * 256 + n] = v;
                } else {
                    float v = acc[i][j] + bias2[n - 256];
                    C2[(size_t)m * 128 + (n - 256)] = v;
                    C3[(size_t)m * 128 + (n - 256)] = v;
                }
            } else {
                float v = acc[i][j] + bias[n];
                if (RESG) v += rres[n];
                if (ACTI == ACT_LEAKY) v = (v > 0.f) ? v : 0.01f * v;
                else if (ACTI == ACT_GELU) v = 0.5f * v * (1.0f + erff(v * 0.70710678118654752f));
                else if (ACTI == ACT_RELU) v = fmaxf(v, 0.f);
                if (QHEAD) qp[i] += v * qwv[n];
                else       C[(size_t)m * N + n] = v;
            }
        }
    }
    if (QHEAD) {
#pragma unroll
        for (int i = 0; i < 2; i++) {
            float s = qp[i];
#pragma unroll
            for (int off = 8; off; off >>= 1) s += __shfl_xor_sync(0xffffffffu, s, off);
            const int m = m0 + ty * 2 + i;
            if (tx == 0 && m < 2208) qvp[blockIdx.x * MPOST + m] = s;
        }
    }
}

// ============================================================================
// gemm64db (R3-proven, plain variant only) — used for G6 (144 CTAs, full wave)
// ============================================================================
__global__ void __launch_bounds__(256)
gemm64(const float* __restrict__ A, const float* __restrict__ W,
       const float* __restrict__ bias, float* __restrict__ C,
       int M, int N, int K)
{
    __shared__ __align__(16) float As[2][16][64];
    __shared__ __align__(16) float Ws[2][16][64];

    const int tid = threadIdx.x;
    const int tx = tid & 15, ty = tid >> 4;
    const int m0 = blockIdx.y * 64, n0 = blockIdx.x * 64;
    const int lr = tid >> 2, lc = (tid & 3) * 4;

    float acc[4][4];
#pragma unroll
    for (int i = 0; i < 4; i++)
#pragma unroll
        for (int j = 0; j < 4; j++) acc[i][j] = 0.f;

    float4 a_pre = *(const float4*)(A + (size_t)(m0 + lr) * K + lc);
    float4 w_pre = *(const float4*)(W + (size_t)(n0 + lr) * K + lc);
    As[0][lc + 0][lr] = a_pre.x; As[0][lc + 1][lr] = a_pre.y;
    As[0][lc + 2][lr] = a_pre.z; As[0][lc + 3][lr] = a_pre.w;
    Ws[0][lc + 0][lr] = w_pre.x; Ws[0][lc + 1][lr] = w_pre.y;
    Ws[0][lc + 2][lr] = w_pre.z; Ws[0][lc + 3][lr] = w_pre.w;
    __syncthreads();

    int buf = 0;
    for (int k0 = 0; k0 < K; k0 += 16) {
        const bool has_next = (k0 + 16 < K);
        if (has_next) {
            a_pre = *(const float4*)(A + (size_t)(m0 + lr) * K + k0 + 16 + lc);
            w_pre = *(const float4*)(W + (size_t)(n0 + lr) * K + k0 + 16 + lc);
        }
#pragma unroll
        for (int kk = 0; kk < 16; kk++) {
            float4 a = *(const float4*)&As[buf][kk][ty * 4];
            float4 b = *(const float4*)&Ws[buf][kk][tx * 4];
            acc[0][0] += a.x * b.x; acc[0][1] += a.x * b.y; acc[0][2] += a.x * b.z; acc[0][3] += a.x * b.w;
            acc[1][0] += a.y * b.x; acc[1][1] += a.y * b.y; acc[1][2] += a.y * b.z; acc[1][3] += a.y * b.w;
            acc[2][0] += a.z * b.x; acc[2][1] += a.z * b.y; acc[2][2] += a.z * b.z; acc[2][3] += a.z * b.w;
            acc[3][0] += a.w * b.x; acc[3][1] += a.w * b.y; acc[3][2] += a.w * b.z; acc[3][3] += a.w * b.w;
        }
        if (has_next) {
            const int nb = buf ^ 1;
            As[nb][lc + 0][lr] = a_pre.x; As[nb][lc + 1][lr] = a_pre.y;
            As[nb][lc + 2][lr] = a_pre.z; As[nb][lc + 3][lr] = a_pre.w;
            Ws[nb][lc + 0][lr] = w_pre.x; Ws[nb][lc + 1][lr] = w_pre.y;
            Ws[nb][lc + 2][lr] = w_pre.z; Ws[nb][lc + 3][lr] = w_pre.w;
            __syncthreads();
            buf = nb;
        }
    }

#pragma unroll
    for (int i = 0; i < 4; i++) {
        const int m = m0 + ty * 4 + i;
#pragma unroll
        for (int j = 0; j < 4; j++) {
            const int n = n0 + tx * 4 + j;
            C[(size_t)m * N + n] = acc[i][j] + bias[n];
        }
    }
}

// ============================================================================
// fused policy + ea: per CTA (32 rows, 64-col ea n-tile):
//   pass1: policy = gelu(H2 @ aw3^T) (N=32; n0==0 CTA writes out_policy)
//   pass2: ea = [obs | policy] @ eaw^T  -> eoea rows 768+
// ============================================================================
__global__ void __launch_bounds__(256)
fused_pol_ea(const float* __restrict__ H2,
             const float* __restrict__ aw3, const float* __restrict__ ab3,
             const float* __restrict__ obs,
             const float* __restrict__ eaw, const float* __restrict__ eab,
             float* __restrict__ out_policy, float* __restrict__ ea768)
{
    __shared__ __align__(16) float As[2][16][34];
    __shared__ __align__(16) float Ws[2][16][64];
    __shared__ __align__(16) float Pol[32][36];

    const int tid = threadIdx.x;
    const int tx = tid & 15, ty = tid >> 4;
    const int m0 = blockIdx.y * 32, n0 = blockIdx.x * 64;
    const int ar = tid >> 2, ac = (tid & 3) * 4;

    // ---- pass 1: policy (K=128, W = aw3 rows<32 else 0) ----
    {
        float acc[2][4];
#pragma unroll
        for (int i = 0; i < 2; i++)
#pragma unroll
            for (int j = 0; j < 4; j++) acc[i][j] = 0.f;

        auto ldA = [&](int k0) {
            return *(const float4*)(H2 + (size_t)(m0 + ar) * 128 + k0 + ac);
        };
        auto ldW = [&](int k0) {
            if (ar < 32) return *(const float4*)(aw3 + (size_t)ar * 128 + k0 + ac);
            return make_float4(0.f, 0.f, 0.f, 0.f);
        };

        float4 a_pre, w_pre;
        if (tid < 128) a_pre = ldA(0);
        w_pre = ldW(0);
        if (tid < 128) {
            As[0][ac + 0][ar] = a_pre.x; As[0][ac + 1][ar] = a_pre.y;
            As[0][ac + 2][ar] = a_pre.z; As[0][ac + 3][ar] = a_pre.w;
        }
        Ws[0][ac + 0][ar] = w_pre.x; Ws[0][ac + 1][ar] = w_pre.y;
        Ws[0][ac + 2][ar] = w_pre.z; Ws[0][ac + 3][ar] = w_pre.w;
        __syncthreads();

        int buf = 0;
        for (int k0 = 0; k0 < 128; k0 += 16) {
            const bool has_next = (k0 + 16 < 128);
            if (has_next) {
                if (tid < 128) a_pre = ldA(k0 + 16);
                w_pre = ldW(k0 + 16);
            }
#pragma unroll
            for (int kk = 0; kk < 16; kk++) {
                const float2 a = *(const float2*)&As[buf][kk][ty * 2];
                const float4 b = *(const float4*)&Ws[buf][kk][tx * 4];
                acc[0][0] += a.x * b.x; acc[0][1] += a.x * b.y;
                acc[0][2] += a.x * b.z; acc[0][3] += a.x * b.w;
                acc[1][0] += a.y * b.x; acc[1][1] += a.y * b.y;
                acc[1][2] += a.y * b.z; acc[1][3] += a.y * b.w;
            }
            if (has_next) {
                const int nb = buf ^ 1;
                if (tid < 128) {
                    As[nb][ac + 0][ar] = a_pre.x; As[nb][ac + 1][ar] = a_pre.y;
                    As[nb][ac + 2][ar] = a_pre.z; As[nb][ac + 3][ar] = a_pre.w;
                }
                Ws[nb][ac + 0][ar] = w_pre.x; Ws[nb][ac + 1][ar] = w_pre.y;
                Ws[nb][ac + 2][ar] = w_pre.z; Ws[nb][ac + 3][ar] = w_pre.w;
                __syncthreads();
                buf = nb;
            }
        }

        if (tx < 8) {
#pragma unroll
            for (int i = 0; i < 2; i++) {
                const int r = ty * 2 + i;
#pragma unroll
                for (int j = 0; j < 4; j++) {
                    const int n = tx * 4 + j;
                    float v = acc[i][j] + ab3[n];
                    v = 0.5f * v * (1.0f + erff(v * 0.70710678118654752f));
                    Pol[r][n] = v;
                    if (blockIdx.x == 0) out_policy[(size_t)(m0 + r) * 32 + n] = v;
                }
            }
        }
    }
    __syncthreads();   // Pol ready; As/Ws free for reuse

    // ---- pass 2: ea (K=160: obs cols 0..127, policy cols 128..159) ----
    {
        float acc[2][4];
#pragma unroll
        for (int i = 0; i < 2; i++)
#pragma unroll
            for (int j = 0; j < 4; j++) acc[i][j] = 0.f;

        auto ldA = [&](int k0) {
            const int kc = k0 + ac;
            if (kc < 128)
                return *(const float4*)(obs + (size_t)(m0 + ar) * 128 + kc);
            return *(const float4*)&Pol[ar][kc - 128];
        };
        auto ldW = [&](int k0) {
            return *(const float4*)(eaw + (size_t)(n0 + ar) * 160 + k0 + ac);
        };

        float4 a_pre, w_pre;
        if (tid < 128) a_pre = ldA(0);
        w_pre = ldW(0);
        if (tid < 128) {
            As[0][ac + 0][ar] = a_pre.x; As[0][ac + 1][ar] = a_pre.y;
            As[0][ac + 2][ar] = a_pre.z; As[0][ac + 3][ar] = a_pre.w;
        }
        Ws[0][ac + 0][ar] = w_pre.x; Ws[0][ac + 1][ar] = w_pre.y;
        Ws[0][ac + 2][ar] = w_pre.z; Ws[0][ac + 3][ar] = w_pre.w;
        __syncthreads();

        int buf = 0;
        for (int k0 = 0; k0 < 160; k0 += 16) {
            const bool has_next = (k0 + 16 < 160);
            if (has_next) {
                if (tid < 128) a_pre = ldA(k0 + 16);
                w_pre = ldW(k0 + 16);
            }
#pragma unroll
            for (int kk = 0; kk < 16; kk++) {
                const float2 a = *(const float2*)&As[buf][kk][ty * 2];
                const float4 b = *(const float4*)&Ws[buf][kk][tx * 4];
                acc[0][0] += a.x * b.x; acc[0][1] += a.x * b.y;
                acc[0][2] += a.x * b.z; acc[0][3] += a.x * b.w;
                acc[1][0] += a.y * b.x; acc[1][1] += a.y * b.y;
                acc[1][2] += a.y * b.z; acc[1][3] += a.y * b.w;
            }
            if (has_next) {
                const int nb = buf ^ 1;
                if (tid < 128) {
                    As[nb][ac + 0][ar] = a_pre.x; As[nb][ac + 1][ar] = a_pre.y;
                    As[nb][ac + 2][ar] = a_pre.z; As[nb][ac + 3][ar] = a_pre.w;
                }
                Ws[nb][ac + 0][ar] = w_pre.x; Ws[nb][ac + 1][ar] = w_pre.y;
                Ws[nb][ac + 2][ar] = w_pre.z; Ws[nb][ac + 3][ar] = w_pre.w;
                __syncthreads();
                buf = nb;
            }
        }

#pragma unroll
        for (int i = 0; i < 2; i++) {
            const int m = m0 + ty * 2 + i;
#pragma unroll
            for (int j = 0; j < 4; j++) {
                const int n = n0 + tx * 4 + j;
                ea768[(size_t)m * 128 + n] = acc[i][j] + eab[n];
            }
        }
    }
}

// ============================================================================
// combined attention (unchanged from R5): 0..95 flash split-m, 96..155 class
// ============================================================================
struct Flash64Smem {
    float Qs[32][68];
    float Ks[32][68];
    float Vs[64][36];
    float Ss[64][68];
    float Pt[64][68];
    float Ms[64], Ls[64], Cs[64];
};
struct ClsSmem {
    float Qc[96][36];
    float Kc[96][36];
    float Vc[96][36];
    float Sc[96][97];
};
union AttnSmem { Flash64Smem f; ClsSmem c; };

__global__ void __launch_bounds__(256)
attn_combined(const float* __restrict__ qkvd, float* __restrict__ aod,
              float* __restrict__ fO, float* __restrict__ fM, float* __restrict__ fL)
{
    extern __shared__ char raw[];
    const int bx = blockIdx.x;
    const int tid = threadIdx.x;

    if (bx < 96) {
        Flash64Smem& sm = reinterpret_cast<AttnSmem*>(raw)->f;
        const int half = bx / 48;
        const int rem = bx % 48;
        const int h = rem / 12;
        const int l0 = (rem % 12) * 64;
        const float* Qb = qkvd + h * 32;
        const float* Kb = qkvd + 128 + h * 32;
        const float* Vb = qkvd + 256 + h * 32;

#pragma unroll
        for (int t = 0; t < 2; t++) {
            const int f = tid + t * 256;
            const int r = f >> 3, c = (f & 7) * 4;
            float4 v = *(const float4*)(Qb + (size_t)(l0 + r) * QKVW + c);
            sm.Qs[c + 0][r] = v.x; sm.Qs[c + 1][r] = v.y;
            sm.Qs[c + 2][r] = v.z; sm.Qs[c + 3][r] = v.w;
        }
        if (tid < 64) { sm.Ms[tid] = -1e30f; sm.Ls[tid] = 0.f; }

        float O[2][4];
#pragma unroll
        for (int i = 0; i < 2; i++)
#pragma unroll
            for (int j = 0; j < 4; j++) O[i][j] = 0.f;

        const int txA = tid & 15, tyA = tid >> 4;
        const int rB = tid >> 2,  hB = tid & 3;
        const int txC = tid & 7,  tyC = tid >> 3;

        const int mbeg = half * 384;
        for (int m0 = mbeg; m0 < mbeg + 384; m0 += 64) {
            __syncthreads();
#pragma unroll
            for (int t = 0; t < 2; t++) {
                const int f = tid + t * 256;
                const int r = f >> 3, c = (f & 7) * 4;
                float4 kv = *(const float4*)(Kb + (size_t)(m0 + r) * QKVW + c);
                sm.Ks[c + 0][r] = kv.x; sm.Ks[c + 1][r] = kv.y;
                sm.Ks[c + 2][r] = kv.z; sm.Ks[c + 3][r] = kv.w;
                float4 vv = *(const float4*)(Vb + (size_t)(m0 + r) * QKVW + c);
                *(float4*)&sm.Vs[r][c] = vv;
            }
            __syncthreads();

            float fa[4][4];
#pragma unroll
            for (int i = 0; i < 4; i++)
#pragma unroll
                for (int j = 0; j < 4; j++) fa[i][j] = 0.f;
#pragma unroll 8
            for (int d = 0; d < 32; d++) {
                float4 a = *(const float4*)&sm.Qs[d][tyA * 4];
                float4 b = *(const float4*)&sm.Ks[d][txA * 4];
                fa[0][0] += a.x * b.x; fa[0][1] += a.x * b.y; fa[0][2] += a.x * b.z; fa[0][3] += a.x * b.w;
                fa[1][0] += a.y * b.x; fa[1][1] += a.y * b.y; fa[1][2] += a.y * b.z; fa[1][3] += a.y * b.w;
                fa[2][0] += a.z * b.x; fa[2][1] += a.z * b.y; fa[2][2] += a.z * b.z; fa[2][3] += a.z * b.w;
                fa[3][0] += a.w * b.x; fa[3][1] += a.w * b.y; fa[3][2] += a.w * b.z; fa[3][3] += a.w * b.w;
            }
            const float sc = 0.17677669529663687f;
#pragma unroll
            for (int i = 0; i < 4; i++)
#pragma unroll
                for (int j = 0; j < 4; j++)
                    sm.Ss[tyA * 4 + i][txA * 4 + j] = fa[i][j] * sc;
            __syncthreads();

            {
                const float* srow = &sm.Ss[rB][hB * 16];
                float mloc = -1e30f;
#pragma unroll
                for (int j = 0; j < 16; j++) mloc = fmaxf(mloc, srow[j]);
                mloc = fmaxf(mloc, __shfl_xor_sync(0xffffffffu, mloc, 1));
                mloc = fmaxf(mloc, __shfl_xor_sync(0xffffffffu, mloc, 2));
                float m_old = sm.Ms[rB];
                float m_new = fmaxf(m_old, mloc);
                float corr = __expf(m_old - m_new);
                float s = 0.f;
#pragma unroll
                for (int j = 0; j < 16; j++) {
                    float e = __expf(srow[j] - m_new);
                    sm.Pt[hB * 16 + j][rB] = e;
                    s += e;
                }
                s += __shfl_xor_sync(0xffffffffu, s, 1);
                s += __shfl_xor_sync(0xffffffffu, s, 2);
                if (hB == 0) {
                    sm.Ms[rB] = m_new;
                    sm.Ls[rB] = sm.Ls[rB] * corr + s;
                    sm.Cs[rB] = corr;
                }
            }
            __syncthreads();

            const float c0 = sm.Cs[tyC * 2];
            const float c1 = sm.Cs[tyC * 2 + 1];
#pragma unroll
            for (int j = 0; j < 4; j++) { O[0][j] *= c0; O[1][j] *= c1; }
#pragma unroll 8
            for (int mm = 0; mm < 64; mm++) {
                const float a0 = sm.Pt[mm][tyC * 2];
                const float a1 = sm.Pt[mm][tyC * 2 + 1];
                float4 b = *(const float4*)&sm.Vs[mm][txC * 4];
                O[0][0] += a0 * b.x; O[0][1] += a0 * b.y; O[0][2] += a0 * b.z; O[0][3] += a0 * b.w;
                O[1][0] += a1 * b.x; O[1][1] += a1 * b.y; O[1][2] += a1 * b.z; O[1][3] += a1 * b.w;
            }
        }

        const int pb = half * 4 + h;
#pragma unroll
        for (int i = 0; i < 2; i++) {
            const int r = tyC * 2 + i;
            const int l = l0 + r;
            *(float4*)(fO + ((size_t)pb * LL + l) * 32 + txC * 4) = *(float4*)&O[i][0];
            if (txC == 0) {
                fM[(size_t)pb * LL + l] = sm.Ms[r];
                fL[(size_t)pb * LL + l] = sm.Ls[r];
            }
        }
    } else {
        ClsSmem& sm = reinterpret_cast<AttnSmem*>(raw)->c;
        const int idx = bx - 96;
        const int k = idx % 15 + 1;
        const int h = idx / 15;

#pragma unroll
        for (int t = 0; t < 3; t++) {
            const int f = tid + t * 256;
            const int r = f >> 3, c = (f & 7) * 4;
            const int b = r >> 1, cc = r & 1;
            const int j = cc ? (k - 1) : k;
            const float* base = qkvd + (size_t)(768 + b * 16 + j) * QKVW + h * 32 + c;
            *(float4*)&sm.Qc[r][c] = *(const float4*)(base);
            *(float4*)&sm.Kc[r][c] = *(const float4*)(base + 128);
            *(float4*)&sm.Vc[r][c] = *(const float4*)(base + 256);
        }
        __syncthreads();

        const int tx = tid & 15, ty = tid >> 4;
        {
            float acc[6][6];
#pragma unroll
            for (int i = 0; i < 6; i++)
#pragma unroll
                for (int j = 0; j < 6; j++) acc[i][j] = 0.f;
#pragma unroll 8
            for (int d = 0; d < 32; d++) {
                float a[6], b[6];
#pragma unroll
                for (int i = 0; i < 6; i++) a[i] = sm.Qc[ty * 6 + i][d];
#pragma unroll
                for (int j = 0; j < 6; j++) b[j] = sm.Kc[tx * 6 + j][d];
#pragma unroll
                for (int i = 0; i < 6; i++)
#pragma unroll
                    for (int j = 0; j < 6; j++) acc[i][j] += a[i] * b[j];
            }
            const float scl = 0.17677669529663687f;
#pragma unroll
            for (int i = 0; i < 6; i++)
#pragma unroll
                for (int j = 0; j < 6; j++)
                    sm.Sc[ty * 6 + i][tx * 6 + j] = acc[i][j] * scl;
        }
        __syncthreads();

        if (tid < 96) {
            float mx = -1e30f;
#pragma unroll 8
            for (int m = 0; m < 96; m++) mx = fmaxf(mx, sm.Sc[tid][m]);
            const float w0 = (float)k, w1 = (float)(16 - k);
            float s = 0.f;
#pragma unroll 8
            for (int m = 0; m < 96; m++) {
                float w = (m & 1) ? w1 : w0;
                float e = w * __expf(sm.Sc[tid][m] - mx);
                sm.Sc[tid][m] = e;
                s += e;
            }
            const float inv = 1.0f / s;
#pragma unroll 8
            for (int m = 0; m < 96; m++) sm.Sc[tid][m] *= inv;
        }
        __syncthreads();

        const int txo = tid & 7, tyo = tid >> 3;
        float o[3][4];
#pragma unroll
        for (int i = 0; i < 3; i++)
#pragma unroll
            for (int j = 0; j < 4; j++) o[i][j] = 0.f;
#pragma unroll 8
        for (int m = 0; m < 96; m++) {
            float a[3];
#pragma unroll
            for (int i = 0; i < 3; i++) a[i] = sm.Sc[tyo * 3 + i][m];
            float4 b = *(const float4*)&sm.Vc[m][txo * 4];
#pragma unroll
            for (int i = 0; i < 3; i++) {
                o[i][0] += a[i] * b.x; o[i][1] += a[i] * b.y;
                o[i][2] += a[i] * b.z; o[i][3] += a[i] * b.w;
            }
        }
#pragma unroll
        for (int i = 0; i < 3; i++) {
            const int row = 768 + (k - 1) * 96 + tyo * 3 + i;
            *(float4*)(aod + (size_t)row * 128 + h * 32 + txo * 4) = *(float4*)&o[i][0];
        }
    }
}

// ---- assemble q_values from class partials ----
__global__ void assemble(const float* __restrict__ qvp, const float* __restrict__ qb,
                         float* __restrict__ out_q)
{
    const int l = blockIdx.x * 256 + threadIdx.x;
    if (l >= 768) return;
    const int b = l >> 4, i = l & 15;
    const float qb0 = qb[0];
    float s = qvp[l] + qvp[MPOST + l] + qb0;
#pragma unroll
    for (int k = 1; k < 16; k++) {
        const int c = (i < k) ? 0 : 1;
        const int row = 768 + (k - 1) * 96 + b * 2 + c;
        s += qvp[row] + qvp[MPOST + row] + qb0;
    }
    out_q[l] = s;
}

extern "C" void kernel_launch(void* const* d_in, const int* in_sizes, int n_in,
                              void* d_out, int out_size)
{
    const float* obs = (const float*)d_in[0];
    const float* aw1 = (const float*)d_in[1];  const float* ab1 = (const float*)d_in[2];
    const float* aw2 = (const float*)d_in[3];  const float* ab2 = (const float*)d_in[4];
    const float* aw3 = (const float*)d_in[5];  const float* ab3 = (const float*)d_in[6];
    const float* eow = (const float*)d_in[7];  const float* eob = (const float*)d_in[8];
    const float* eaw = (const float*)d_in[9];  const float* eab = (const float*)d_in[10];
    const float* riw = (const float*)d_in[11]; const float* rib = (const float*)d_in[12];
    const float* roww = (const float*)d_in[13]; const float* rob = (const float*)d_in[14];
    const float* miw = (const float*)d_in[15]; const float* mib = (const float*)d_in[16];
    const float* mow = (const float*)d_in[17]; const float* mob = (const float*)d_in[18];
    const float* qw  = (const float*)d_in[19]; const float* qb  = (const float*)d_in[20];

    float* out = (float*)d_out;
    float* out_policy = out + OUT_POLICY;
    float* out_q      = out + OUT_Q;
    float* out_eo     = out + OUT_EO;

    float *H1, *H2, *eoea, *x1d, *qkvd, *aod, *aopd, *qvp, *fO, *fM, *fL;
    cudaGetSymbolAddress((void**)&H1, g_H1);
    cudaGetSymbolAddress((void**)&H2, g_H2);
    cudaGetSymbolAddress((void**)&eoea, g_eoea);
    cudaGetSymbolAddress((void**)&x1d, g_x1d);
    cudaGetSymbolAddress((void**)&qkvd, g_qkvd);
    cudaGetSymbolAddress((void**)&aod, g_aod);
    cudaGetSymbolAddress((void**)&aopd, g_aopd);
    cudaGetSymbolAddress((void**)&qvp, g_qvp);
    cudaGetSymbolAddress((void**)&fO, g_fO);
    cudaGetSymbolAddress((void**)&fM, g_fM);
    cudaGetSymbolAddress((void**)&fL, g_fL);

    cudaFuncSetAttribute(attn_combined, cudaFuncAttributeMaxDynamicSharedMemorySize,
                         (int)sizeof(AttnSmem));

    dim3 blk(256);

    // G1: obs @ [aw1 | eow] -> H1 (leaky, stride 256) + eo (dual write)   144 CTAs
    gemm32<ACT_NONE, true, false, false, false><<<dim3(6, 24), blk>>>(
        obs, aw1, eow, ab1, eob, nullptr, nullptr, nullptr, nullptr, nullptr, nullptr,
        H1, out_eo, eoea, LL, 384, 128);
    // G2: H2 = leaky(H1 @ aw2^T)                                           48 CTAs
    gemm32<ACT_LEAKY, false, false, false, false><<<dim3(2, 24), blk>>>(
        H1, aw2, nullptr, ab2, nullptr, nullptr, nullptr, nullptr, nullptr, nullptr, nullptr,
        H2, nullptr, nullptr, LL, 128, 256);
    // G3+G4 fused: policy + ea                                             48 CTAs
    fused_pol_ea<<<dim3(2, 24), blk>>>(H2, aw3, ab3, obs, eaw, eab,
                                       out_policy, eoea + 768 * 128);
    // G5: x1 distinct rows                                                 96 CTAs
    gemm32<ACT_RELU, false, false, false, false><<<dim3(2, 48), blk>>>(
        eoea, riw, nullptr, rib, nullptr, nullptr, nullptr, nullptr, nullptr, nullptr, nullptr,
        x1d, nullptr, nullptr, 1536, 128, 128);
    // G6: qkv distinct rows (64-tile, full wave)                          144 CTAs
    gemm64<<<dim3(6, 24), blk>>>(x1d, miw, mib, qkvd, 1536, 384, 128);

    // attention: flash split-m partials + class attn, one launch          156 CTAs
    attn_combined<<<156, blk, sizeof(AttnSmem)>>>(qkvd, aod, fO, fM, fL);

    // G7: out_proj + residual, flash rows combined in-loader              140 CTAs
    gemm32<ACT_NONE, false, true, true, false><<<dim3(2, 70), blk>>>(
        aod, mow, nullptr, mob, nullptr, x1d, fO, fM, fL, nullptr, nullptr,
        aopd, nullptr, nullptr, MPOST, 128, 128);
    // G8: output layer + fused q-head partial dot                         140 CTAs
    gemm32<ACT_RELU, false, false, false, true><<<dim3(2, 70), blk>>>(
        aopd, roww, nullptr, rob, nullptr, nullptr, nullptr, nullptr, nullptr, qw, qvp,
        nullptr, nullptr, nullptr, MPOST, 128, 128);

    assemble<<<3, blk>>>(qvp, qb, out_q);

    (void)in_sizes; (void)n_in; (void)out_size;
}